// round 15
// baseline (speedup 1.0000x reference)
#include <cuda_runtime.h>
#include <cstdint>

#define N_NODES 100000
#define DIM 16
#define NF   (N_NODES * DIM)       // total floats in node matrix
#define N4   (NF / 4)              // float4 count

// Edge-message accumulator (holds sum of x[src]*prob, WITHOUT the weight
// factor — weight commutes with the segment-sum and is applied in finalize).
// Zero-initialized at module load; finalize re-zeros it every call.
__device__ float4 g_acc[N4];

// ---------------------------------------------------------------------------
// Kernel 1: scatter — measured-best configuration (R7/R13: ~54.8us, the
// REDG per-lane issue floor for 12.8M RED.E.128 lane-ops).
// 4 threads per edge (thread = one 16B chunk of the row). Per-block dtype
// detect: threads 0..63 read the first 64 8-byte words of edge_index; if the
// buffer is int32, the high words are random node ids -> almost surely
// outside [0, N_NODES); all-in-range <=> int64. T=256 with one __syncthreads
// (per-warp detect and T=512 both measured worse).
// Lanes 4k..4k+3 read consecutive 16B of x[src] -> a warp's gather touches 8
// random rows instead of 32. One red.global.add.v4.f32 per thread (no-return
// 128b L2 reduction) — max reduction width, minimal lane count.
// ---------------------------------------------------------------------------
__global__ void __launch_bounds__(256)
ldl_scatter_kernel(const float4* __restrict__ x,
                   const void* __restrict__ eidx,
                   const float* __restrict__ probs,
                   int E) {
    __shared__ int s_ok[2];
    {
        int tid = threadIdx.x;
        if (tid < 64) {
            long long v = ((const long long*)eidx)[tid];
            bool ok = (v >= 0 && v < N_NODES);
            unsigned b = __ballot_sync(0xFFFFFFFFu, ok);
            if ((tid & 31) == 0) s_ok[tid >> 5] = (b == 0xFFFFFFFFu);
        }
        __syncthreads();
    }
    bool is64 = (s_ok[0] && s_ok[1]);

    int t = blockIdx.x * blockDim.x + threadIdx.x;
    int e = t >> 2;
    int c = t & 3;
    if (e >= E) return;

    long long s, d;
    if (is64) {
        const long long* p = (const long long*)eidx;
        s = __ldg(p + e);
        d = __ldg(p + E + e);
    } else {
        const int* p = (const int*)eidx;
        s = __ldg(p + e);
        d = __ldg(p + E + e);
    }
    if (s < 0 || s >= N_NODES || d < 0 || d >= N_NODES) return;  // backstop

    float pr = __ldg(probs + e);
    float4 xv = __ldg(x + s * 4 + c);

    float a0 = xv.x * pr;
    float a1 = xv.y * pr;
    float a2 = xv.z * pr;
    float a3 = xv.w * pr;
    float* op = (float*)g_acc + d * DIM + c * 4;
    asm volatile(
        "red.global.add.v4.f32 [%0], {%1, %2, %3, %4};"
        :: "l"(op), "f"(a0), "f"(a1), "f"(a2), "f"(a3)
        : "memory");
}

// ---------------------------------------------------------------------------
// Kernel 2: finalize — out = clip(x*(1+slw) + acc*weight, 0, 1), re-zero
// acc for the next replay. 1 float4/thread, 1563 blocks (measured best:
// max parallelism beats per-thread MLP for this latency-bound stream; the
// 2-per-thread variant measured 8.0us vs 6.6us). Weight load is a
// warp-broadcast L1 hit; weight applied post-sum by linearity.
// ---------------------------------------------------------------------------
__global__ void __launch_bounds__(256)
ldl_final_kernel(const float4* __restrict__ x,
                 const float* __restrict__ weight,
                 const float* __restrict__ slw,
                 float4* __restrict__ out) {
    int i = blockIdx.x * blockDim.x + threadIdx.x;
    if (i < N4) {
        float s = 1.0f + __ldg(slw);
        float4 wv = __ldg((const float4*)weight + (i & 3));
        float4 xv = x[i];
        float4 av = g_acc[i];
        float4 v;
        v.x = fminf(fmaxf(fmaf(av.x, wv.x, xv.x * s), 0.0f), 1.0f);
        v.y = fminf(fmaxf(fmaf(av.y, wv.y, xv.y * s), 0.0f), 1.0f);
        v.z = fminf(fmaxf(fmaf(av.z, wv.z, xv.z * s), 0.0f), 1.0f);
        v.w = fminf(fmaxf(fmaf(av.w, wv.w, xv.w * s), 0.0f), 1.0f);
        out[i] = v;
        g_acc[i] = make_float4(0.0f, 0.0f, 0.0f, 0.0f);
    }
}

// ---------------------------------------------------------------------------
// Launch. Inputs (metadata order):
//   d_in[0] x                [N_NODES, 16] float32
//   d_in[1] edge_index       [2, E]        int64 OR int32 (runtime-detected)
//   d_in[2] edge_probs       [E]           float32
//   d_in[3] weight           [16]          float32
//   d_in[4] self_loop_weight scalar        float32
// Graph: [scatter -> finalize]; accumulator scratch keeps the init stream
// off the critical path; weight applied post-sum (linearity).
// ---------------------------------------------------------------------------
extern "C" void kernel_launch(void* const* d_in, const int* in_sizes, int n_in,
                              void* d_out, int out_size) {
    const float4* x     = (const float4*)d_in[0];
    const void*   eidx  = d_in[1];
    const float*  probs = (const float*)d_in[2];
    const float*  w     = (const float*)d_in[3];
    const float*  slw   = (const float*)d_in[4];
    float*        out   = (float*)d_out;

    const int E = in_sizes[2];   // edge_probs element count
    const int T = 256;

    long long n = 4LL * E;
    int gScat = (int)((n + T - 1) / T);
    ldl_scatter_kernel<<<gScat, T>>>(x, eidx, probs, E);

    int gFin = (N4 + T - 1) / T;
    ldl_final_kernel<<<gFin, T>>>(x, w, slw, (float4*)out);
}

// round 16
// speedup vs baseline: 1.0026x; 1.0026x over previous
#include <cuda_runtime.h>
#include <cstdint>

#define N_NODES 100000
#define DIM 16
#define NF   (N_NODES * DIM)       // total floats in node matrix
#define N4   (NF / 4)              // float4 count

// Edge-message accumulator (holds sum of x[src]*prob, WITHOUT the weight
// factor — weight commutes with the segment-sum and is applied in finalize).
// Zero-initialized at module load; finalize re-zeros it every call.
__device__ float4 g_acc[N4];

// ---------------------------------------------------------------------------
// Kernel 1: scatter — measured-best configuration (R7/R13/R14/R15: ~54.8us,
// the REDG per-lane issue floor for 12.8M RED.E.128 lane-ops).
// 4 threads per edge (thread = one 16B chunk of the row). Per-block dtype
// detect: threads 0..63 read the first 64 8-byte words of edge_index; if the
// buffer is int32, the high words are random node ids -> almost surely
// outside [0, N_NODES); all-in-range <=> int64. T=256 with one __syncthreads
// (per-warp detect and T=512 both measured worse).
// Lanes 4k..4k+3 read consecutive 16B of x[src] -> a warp's gather touches 8
// random rows instead of 32. One red.global.add.v4.f32 per thread (no-return
// 128b L2 reduction) — max reduction width, minimal lane count.
// ---------------------------------------------------------------------------
__global__ void __launch_bounds__(256)
ldl_scatter_kernel(const float4* __restrict__ x,
                   const void* __restrict__ eidx,
                   const float* __restrict__ probs,
                   int E) {
    __shared__ int s_ok[2];
    {
        int tid = threadIdx.x;
        if (tid < 64) {
            long long v = ((const long long*)eidx)[tid];
            bool ok = (v >= 0 && v < N_NODES);
            unsigned b = __ballot_sync(0xFFFFFFFFu, ok);
            if ((tid & 31) == 0) s_ok[tid >> 5] = (b == 0xFFFFFFFFu);
        }
        __syncthreads();
    }
    bool is64 = (s_ok[0] && s_ok[1]);

    int t = blockIdx.x * blockDim.x + threadIdx.x;
    int e = t >> 2;
    int c = t & 3;
    if (e >= E) return;

    long long s, d;
    if (is64) {
        const long long* p = (const long long*)eidx;
        s = __ldg(p + e);
        d = __ldg(p + E + e);
    } else {
        const int* p = (const int*)eidx;
        s = __ldg(p + e);
        d = __ldg(p + E + e);
    }
    if (s < 0 || s >= N_NODES || d < 0 || d >= N_NODES) return;  // backstop

    float pr = __ldg(probs + e);
    float4 xv = __ldg(x + s * 4 + c);

    float a0 = xv.x * pr;
    float a1 = xv.y * pr;
    float a2 = xv.z * pr;
    float a3 = xv.w * pr;
    float* op = (float*)g_acc + d * DIM + c * 4;
    asm volatile(
        "red.global.add.v4.f32 [%0], {%1, %2, %3, %4};"
        :: "l"(op), "f"(a0), "f"(a1), "f"(a2), "f"(a3)
        : "memory");
}

// ---------------------------------------------------------------------------
// Kernel 2: finalize — out = clip(x*(1+slw) + acc*weight, 0, 1), re-zero
// acc for the next replay. 1 float4/thread, 1563 blocks (measured best:
// max parallelism beats per-thread MLP for this latency-bound stream; the
// 2-per-thread variant measured 8.0us vs 6.6us). Weight load is a
// warp-broadcast L1 hit; weight applied post-sum by linearity.
// ---------------------------------------------------------------------------
__global__ void __launch_bounds__(256)
ldl_final_kernel(const float4* __restrict__ x,
                 const float* __restrict__ weight,
                 const float* __restrict__ slw,
                 float4* __restrict__ out) {
    int i = blockIdx.x * blockDim.x + threadIdx.x;
    if (i < N4) {
        float s = 1.0f + __ldg(slw);
        float4 wv = __ldg((const float4*)weight + (i & 3));
        float4 xv = x[i];
        float4 av = g_acc[i];
        float4 v;
        v.x = fminf(fmaxf(fmaf(av.x, wv.x, xv.x * s), 0.0f), 1.0f);
        v.y = fminf(fmaxf(fmaf(av.y, wv.y, xv.y * s), 0.0f), 1.0f);
        v.z = fminf(fmaxf(fmaf(av.z, wv.z, xv.z * s), 0.0f), 1.0f);
        v.w = fminf(fmaxf(fmaf(av.w, wv.w, xv.w * s), 0.0f), 1.0f);
        out[i] = v;
        g_acc[i] = make_float4(0.0f, 0.0f, 0.0f, 0.0f);
    }
}

// ---------------------------------------------------------------------------
// Launch. Inputs (metadata order):
//   d_in[0] x                [N_NODES, 16] float32
//   d_in[1] edge_index       [2, E]        int64 OR int32 (runtime-detected)
//   d_in[2] edge_probs       [E]           float32
//   d_in[3] weight           [16]          float32
//   d_in[4] self_loop_weight scalar        float32
// Graph: [scatter -> finalize]; accumulator scratch keeps the init stream
// off the critical path; weight applied post-sum (linearity).
// ---------------------------------------------------------------------------
extern "C" void kernel_launch(void* const* d_in, const int* in_sizes, int n_in,
                              void* d_out, int out_size) {
    const float4* x     = (const float4*)d_in[0];
    const void*   eidx  = d_in[1];
    const float*  probs = (const float*)d_in[2];
    const float*  w     = (const float*)d_in[3];
    const float*  slw   = (const float*)d_in[4];
    float*        out   = (float*)d_out;

    const int E = in_sizes[2];   // edge_probs element count
    const int T = 256;

    long long n = 4LL * E;
    int gScat = (int)((n + T - 1) / T);
    ldl_scatter_kernel<<<gScat, T>>>(x, eidx, probs, E);

    int gFin = (N4 + T - 1) / T;
    ldl_final_kernel<<<gFin, T>>>(x, w, slw, (float4*)out);
}